// round 2
// baseline (speedup 1.0000x reference)
#include <cuda_runtime.h>

// Output = segment_sum(source[src_idx], seg_ids): softmax over the singleton
// axis is identically 1.0, so all attention machinery is dead code.
//
// Inputs (metadata order):
//  0: source  [N,64] f32
//  1: target  [N,64] f32   (unused)
//  2: src_idx [E]    int32 (jax x64 disabled -> int64 request degrades to int32)
//  3: seg_ids [E]    int32 (sorted)
//  4..9: linear params (unused)

#define EDGES_PER_WARP 128

__global__ void zero_out_kernel(float4* __restrict__ out4, int n4) {
    int i = blockIdx.x * blockDim.x + threadIdx.x;
    int stride = gridDim.x * blockDim.x;
    for (int j = i; j < n4; j += stride)
        out4[j] = make_float4(0.f, 0.f, 0.f, 0.f);
}

__global__ void __launch_bounds__(256)
seg_gather_sum_kernel(const float2* __restrict__ src2,
                      const int* __restrict__ src_idx,
                      const int* __restrict__ seg_ids,
                      float* __restrict__ out,
                      int E) {
    const int lane = threadIdx.x & 31;
    const int warp = blockIdx.x * (blockDim.x >> 5) + (threadIdx.x >> 5);
    int e0 = warp * EDGES_PER_WARP;
    if (e0 >= E) return;
    int e1 = e0 + EDGES_PER_WARP;
    if (e1 > E) e1 = E;

    int cur = seg_ids[e0];
    float ax = 0.f, ay = 0.f;

    int e = e0;
    // 4-way unrolled main body: batch-issue 4 independent gathers (MLP=4)
    for (; e + 4 <= e1; e += 4) {
        int s0 = seg_ids[e + 0];
        int s1 = seg_ids[e + 1];
        int s2 = seg_ids[e + 2];
        int s3 = seg_ids[e + 3];
        int i0 = src_idx[e + 0];
        int i1 = src_idx[e + 1];
        int i2 = src_idx[e + 2];
        int i3 = src_idx[e + 3];
        float2 v0 = __ldg(&src2[(long long)i0 * 32 + lane]);
        float2 v1 = __ldg(&src2[(long long)i1 * 32 + lane]);
        float2 v2 = __ldg(&src2[(long long)i2 * 32 + lane]);
        float2 v3 = __ldg(&src2[(long long)i3 * 32 + lane]);

        if (s0 != cur) {
            atomicAdd(&out[(long long)cur * 64 + 2 * lane + 0], ax);
            atomicAdd(&out[(long long)cur * 64 + 2 * lane + 1], ay);
            ax = 0.f; ay = 0.f; cur = s0;
        }
        ax += v0.x; ay += v0.y;
        if (s1 != cur) {
            atomicAdd(&out[(long long)cur * 64 + 2 * lane + 0], ax);
            atomicAdd(&out[(long long)cur * 64 + 2 * lane + 1], ay);
            ax = 0.f; ay = 0.f; cur = s1;
        }
        ax += v1.x; ay += v1.y;
        if (s2 != cur) {
            atomicAdd(&out[(long long)cur * 64 + 2 * lane + 0], ax);
            atomicAdd(&out[(long long)cur * 64 + 2 * lane + 1], ay);
            ax = 0.f; ay = 0.f; cur = s2;
        }
        ax += v2.x; ay += v2.y;
        if (s3 != cur) {
            atomicAdd(&out[(long long)cur * 64 + 2 * lane + 0], ax);
            atomicAdd(&out[(long long)cur * 64 + 2 * lane + 1], ay);
            ax = 0.f; ay = 0.f; cur = s3;
        }
        ax += v3.x; ay += v3.y;
    }
    // tail
    for (; e < e1; ++e) {
        int s = seg_ids[e];
        int idx = src_idx[e];
        float2 v = __ldg(&src2[(long long)idx * 32 + lane]);
        if (s != cur) {
            atomicAdd(&out[(long long)cur * 64 + 2 * lane + 0], ax);
            atomicAdd(&out[(long long)cur * 64 + 2 * lane + 1], ay);
            ax = 0.f; ay = 0.f; cur = s;
        }
        ax += v.x; ay += v.y;
    }
    // final flush
    atomicAdd(&out[(long long)cur * 64 + 2 * lane + 0], ax);
    atomicAdd(&out[(long long)cur * 64 + 2 * lane + 1], ay);
}

extern "C" void kernel_launch(void* const* d_in, const int* in_sizes, int n_in,
                              void* d_out, int out_size) {
    const float* source  = (const float*)d_in[0];
    const int*   src_idx = (const int*)d_in[2];
    const int*   seg_ids = (const int*)d_in[3];
    float* out = (float*)d_out;

    int E = in_sizes[2];

    // 1) zero the output (poisoned by harness; empty segments must be 0)
    int n4 = out_size / 4;
    int zthreads = 256;
    int zblocks = (n4 + zthreads - 1) / zthreads;
    if (zblocks > 1184) zblocks = 1184;  // grid-stride
    zero_out_kernel<<<zblocks, zthreads>>>((float4*)d_out, n4);

    // 2) gather + segment-sum
    int nwarps = (E + EDGES_PER_WARP - 1) / EDGES_PER_WARP;
    int threads = 256;  // 8 warps
    int nblocks = (nwarps + 7) / 8;
    seg_gather_sum_kernel<<<nblocks, threads>>>(
        (const float2*)source, src_idx, seg_ids, out, E);
}